// round 10
// baseline (speedup 1.0000x reference)
#include <cuda_runtime.h>
#include <cuda_bf16.h>
#include <cuda_fp16.h>
#include <math.h>
#include <stdint.h>

// Problem constants
#define BB   4
#define TT   512
#define HH   2048
#define VV   32000
#define BT   (BB*TT)          // 2048 rows
#define NCTAY 250
#define CANDP 256             // padded stride for candidate table
#define BETA_C   0.1f
#define EPS_LO_C 0.2f
#define EPS_HI_C 0.2f

// GEMM tiling (legacy mma.sync path; tcgen05 not available on this target)
#define BM 128
#define BN 128
#define KC 32                  // K chunk in fp16 elems
#define NCHUNK (HH/KC)         // 64
#define NST 3                  // 3 x 20KB = 60KB -> still 2 CTAs/SM; 2-deep prefetch
#define PITCH 80               // conflict-free smem pitch for LDSM
#define A_OFF  0
#define BH_OFF 10240
#define STAGE_BYTES 20480
#define SMEM_DYN (NST*STAGE_BYTES)   // 61440

// ---------------- scratch (static device globals; no allocations) ----------------
__device__ float              g_sum_pol[BT];
__device__ float              g_sum_ref[BT];
__device__ unsigned long long g_cand[BT*CANDP];   // per (row, ctaY) noisy max
__device__ uint4              g_top[BT];          // top-3 candidate cols per row (w unused)
__device__ float              g_pdot[BT];
__device__ float              g_rdot[BT];
__device__ __align__(1024) __half g_xh [BT*HH];
__device__ __align__(1024) __half g_wh [(size_t)VV*HH];
__device__ __align__(1024) __half g_rxh[BT*HH];
__device__ __align__(1024) __half g_rwh[(size_t)VV*HH];

// ---------------- PTX helpers ----------------
__device__ __forceinline__ uint32_t s2u(const void* p) {
    uint32_t a;
    asm("{ .reg .u64 t; cvta.to.shared.u64 t, %1; cvt.u32.u64 %0, t; }" : "=r"(a) : "l"(p));
    return a;
}
__device__ __forceinline__ void cpasync16(uint32_t s, const void* g) {
    asm volatile("cp.async.cg.shared.global [%0], [%1], 16;" :: "r"(s), "l"(g) : "memory");
}
__device__ __forceinline__ void cp_commit() {
    asm volatile("cp.async.commit_group;" ::: "memory");
}
template <int N>
__device__ __forceinline__ void cp_wait() {
    asm volatile("cp.async.wait_group %0;" :: "n"(N) : "memory");
}
__device__ __forceinline__ void ldsm4(uint32_t* r, uint32_t a) {
    asm volatile("ldmatrix.sync.aligned.m8n8.x4.shared.b16 {%0,%1,%2,%3}, [%4];"
                 : "=r"(r[0]), "=r"(r[1]), "=r"(r[2]), "=r"(r[3]) : "r"(a));
}
__device__ __forceinline__ void mma16816(float* d, const uint32_t* a, const uint32_t* b) {
    asm volatile(
        "mma.sync.aligned.m16n8k16.row.col.f32.f16.f16.f32 "
        "{%0,%1,%2,%3}, {%4,%5,%6,%7}, {%8,%9}, {%0,%1,%2,%3};"
        : "+f"(d[0]), "+f"(d[1]), "+f"(d[2]), "+f"(d[3])
        : "r"(a[0]), "r"(a[1]), "r"(a[2]), "r"(a[3]), "r"(b[0]), "r"(b[1]));
}
__device__ __forceinline__ unsigned fkey(float f) {
    unsigned u = __float_as_uint(f);
    return (u & 0x80000000u) ? ~u : (u | 0x80000000u);
}
// FMA-only exp
__device__ __forceinline__ float fexp(float x) {
    float t = x * 1.4426950408889634f;
    float r = rintf(t);
    float u = (t - r) * 0.6931471805599453f;
    float p = 8.3333333e-3f;
    p = fmaf(p, u, 4.1666667e-2f);
    p = fmaf(p, u, 1.6666667e-1f);
    p = fmaf(p, u, 0.5f);
    p = fmaf(p, u, 1.0f);
    p = fmaf(p, u, 1.0f);
    int e = (int)r;
    return p * __int_as_float((e + 127) << 23);
}

// ---------------- init ----------------
__global__ void init_kernel() {
    int i = blockIdx.x * blockDim.x + threadIdx.x;
    if (i < BT) { g_sum_pol[i] = 0.0f; g_sum_ref[i] = 0.0f; }
    if (i < BT * CANDP) g_cand[i] = 0ull;
}

// ---------------- convert: fp32 -> fp16 (16 elems/thread for MLP) ----------------
__global__ void convert_h(const float* __restrict__ src, __half* __restrict__ dst, int n16) {
    int i = blockIdx.x * blockDim.x + threadIdx.x;
    if (i >= n16) return;
    float4 v0 = ((const float4*)src)[4*i];
    float4 v1 = ((const float4*)src)[4*i+1];
    float4 v2 = ((const float4*)src)[4*i+2];
    float4 v3 = ((const float4*)src)[4*i+3];
    __half2 h[8];
    h[0] = __floats2half2_rn(v0.x, v0.y);
    h[1] = __floats2half2_rn(v0.z, v0.w);
    h[2] = __floats2half2_rn(v1.x, v1.y);
    h[3] = __floats2half2_rn(v1.z, v1.w);
    h[4] = __floats2half2_rn(v2.x, v2.y);
    h[5] = __floats2half2_rn(v2.z, v2.w);
    h[6] = __floats2half2_rn(v3.x, v3.y);
    h[7] = __floats2half2_rn(v3.z, v3.w);
    ((uint4*)dst)[2*i]   = *(uint4*)&h[0];
    ((uint4*)dst)[2*i+1] = *(uint4*)&h[4];
}

// ---------------- single-fp16 tensor-core GEMM + fused softmax-stats ----------------
__global__ void __launch_bounds__(256, 2)
gemm_mma(const __half* __restrict__ Ah, const __half* __restrict__ Bh,
         float* __restrict__ sumexp, unsigned long long* __restrict__ cand,
         int do_max) {
    extern __shared__ char smem[];
    const uint32_t sb = s2u(smem);
    const int tid  = threadIdx.x;
    const int lane = tid & 31;
    const int wid  = tid >> 5;
    const int wm   = wid >> 2;
    const int wn   = wid & 3;
    const int m0 = blockIdx.x * BM;
    const int n0 = blockIdx.y * BN;

    float acc[4][4][4];
#pragma unroll
    for (int mt = 0; mt < 4; ++mt)
#pragma unroll
        for (int nt = 0; nt < 4; ++nt)
#pragma unroll
            for (int j = 0; j < 4; ++j) acc[mt][nt][j] = 0.0f;

    // cp.async: 1024 16B-chunks per stage = 4/thread (A:512, Bh:512)
    const int c0r = tid >> 2,  c0c = tid & 3;
    const int c1r = c0r + 64;

    auto load_stage = [&](int st, int k0) {
        uint32_t stb = sb + st * STAGE_BYTES;
        {
            uint32_t so = c0r * PITCH + c0c * 16;
            size_t ga = (size_t)(m0 + c0r) * HH + k0 + c0c * 8;
            size_t gb = (size_t)(n0 + c0r) * HH + k0 + c0c * 8;
            cpasync16(stb + A_OFF  + so, Ah + ga);
            cpasync16(stb + BH_OFF + so, Bh + gb);
        }
        {
            uint32_t so = c1r * PITCH + c0c * 16;
            size_t ga = (size_t)(m0 + c1r) * HH + k0 + c0c * 8;
            size_t gb = (size_t)(n0 + c1r) * HH + k0 + c0c * 8;
            cpasync16(stb + A_OFF  + so, Ah + ga);
            cpasync16(stb + BH_OFF + so, Bh + gb);
        }
    };

    // prologue: chunks 0,1 -> stages 0,1
    load_stage(0, 0);  cp_commit();
    load_stage(1, KC); cp_commit();

    const int arow_base = wm * 64 + (lane & 15);
    const int a_half    = (lane >> 4);
    const int brow_base = wn * 32 + ((lane >> 4) & 1) * 8 + (lane & 7);
    const int bksel     = (lane >> 3) & 1;

    int cst = 0;             // c % NST
    int lst = 2;             // (c+2) % NST
    for (int c = 0; c < NCHUNK; ++c) {
        // stage lst was last read in iteration c-1 (ended with __syncthreads)
        if (c + 2 < NCHUNK) load_stage(lst, (c + 2) * KC);
        cp_commit();
        cp_wait<2>();        // chunk c resident; c+1, c+2 may be in flight
        __syncthreads();

        uint32_t stb = sb + cst * STAGE_BYTES;
#pragma unroll
        for (int ks = 0; ks < 2; ++ks) {
            uint32_t acol = (ks * 2 + a_half) * 16;
            uint32_t bcol = (ks * 2 + bksel) * 16;
            uint32_t ah[4][4], bh[2][4];
#pragma unroll
            for (int mt = 0; mt < 4; ++mt)
                ldsm4(ah[mt], stb + A_OFF + (uint32_t)(arow_base + mt * 16) * PITCH + acol);
#pragma unroll
            for (int p = 0; p < 2; ++p)
                ldsm4(bh[p], stb + BH_OFF + (uint32_t)(brow_base + p * 16) * PITCH + bcol);
#pragma unroll
            for (int mt = 0; mt < 4; ++mt)
#pragma unroll
                for (int nt = 0; nt < 4; ++nt)
                    mma16816(acc[mt][nt], ah[mt], &bh[nt >> 1][(nt & 1) * 2]);
        }
        __syncthreads();
        cst = (cst == NST - 1) ? 0 : cst + 1;
        lst = (lst == NST - 1) ? 0 : lst + 1;
    }

    // ---- epilogue: row-wise sum(exp); policy also records CTA-local row max ----
#pragma unroll
    for (int mt = 0; mt < 4; ++mt) {
#pragma unroll
        for (int half = 0; half < 2; ++half) {
            int row = m0 + wm * 64 + mt * 16 + (lane >> 2) + half * 8;
            float s = 0.0f;
            float vmax = -3.402823466e+38f;
            unsigned am = 0;
#pragma unroll
            for (int nt = 0; nt < 4; ++nt)
#pragma unroll
                for (int j = 0; j < 2; ++j) {
                    float v = acc[mt][nt][half * 2 + j];
                    s += fexp(v);
                    unsigned col = (unsigned)(n0 + wn * 32 + nt * 8 + (lane & 3) * 2 + j);
                    if (v > vmax) { vmax = v; am = col; }
                }
#pragma unroll
            for (int m = 1; m < 4; m <<= 1) {
                s += __shfl_xor_sync(0xFFFFFFFFu, s, m);
                float ov = __shfl_xor_sync(0xFFFFFFFFu, vmax, m);
                unsigned oa = __shfl_xor_sync(0xFFFFFFFFu, am, m);
                if (ov > vmax || (ov == vmax && oa < am)) { vmax = ov; am = oa; }
            }
            if ((lane & 3) == 0) {
                atomicAdd(&sumexp[row], s);
                if (do_max) {
                    unsigned long long p = ((unsigned long long)fkey(vmax) << 32)
                                         | (unsigned long long)(0xFFFFFFFFu - am);
                    atomicMax(&cand[(size_t)row * CANDP + blockIdx.y], p);
                }
            }
        }
    }
}

// ---------------- global top-3 candidates per row ----------------
__global__ void top3_kernel() {
    __shared__ unsigned long long sv[256];
    int row = blockIdx.x;
    int tid = threadIdx.x;
    unsigned long long v = (tid < NCTAY) ? g_cand[(size_t)row * CANDP + tid] : 0ull;
    sv[tid] = v; __syncthreads();
    for (int s = 128; s > 0; s >>= 1) {
        if (tid < s) sv[tid] = (sv[tid] > sv[tid + s]) ? sv[tid] : sv[tid + s];
        __syncthreads();
    }
    unsigned long long m1 = sv[0];
    __syncthreads();
    sv[tid] = (v == m1) ? 0ull : v; __syncthreads();
    for (int s = 128; s > 0; s >>= 1) {
        if (tid < s) sv[tid] = (sv[tid] > sv[tid + s]) ? sv[tid] : sv[tid + s];
        __syncthreads();
    }
    unsigned long long m2 = sv[0];
    __syncthreads();
    sv[tid] = (v == m1 || v == m2) ? 0ull : v; __syncthreads();
    for (int s = 128; s > 0; s >>= 1) {
        if (tid < s) sv[tid] = (sv[tid] > sv[tid + s]) ? sv[tid] : sv[tid + s];
        __syncthreads();
    }
    if (tid == 0) {
        unsigned long long m3 = sv[0];
        unsigned c1 = 0xFFFFFFFFu - (unsigned)(m1 & 0xFFFFFFFFull);
        unsigned c2 = (m2 != 0ull) ? (0xFFFFFFFFu - (unsigned)(m2 & 0xFFFFFFFFull)) : c1;
        unsigned c3 = (m3 != 0ull) ? (0xFFFFFFFFu - (unsigned)(m3 & 0xFFFFFFFFull)) : c1;
        g_top[row] = make_uint4(c1, c2, c3, 0u);
    }
}

// ---------------- exact fp32 dots for top-3, pick true argmax ----------------
__global__ void gather_pick(const float* __restrict__ x, const float* __restrict__ w,
                            const float* __restrict__ rx, const float* __restrict__ rw) {
    __shared__ float sd[6];
    int row = blockIdx.x;
    int tid = threadIdx.x;
    int wrp = tid >> 5;         // 0..5: (model, cand) = (wrp/3, wrp%3)
    int lane = tid & 31;
    uint4 t = g_top[row];
    unsigned cols[3] = { t.x, t.y, t.z };
    unsigned col = cols[wrp % 3];
    const float* a = (wrp < 3) ? (x + (size_t)row * HH) : (rx + (size_t)row * HH);
    const float* b = (wrp < 3) ? (w + (size_t)col * HH) : (rw + (size_t)col * HH);
    float s = 0.0f;
    for (int h = lane; h < HH; h += 32) s = fmaf(a[h], b[h], s);
#pragma unroll
    for (int m = 16; m >= 1; m >>= 1) s += __shfl_xor_sync(0xFFFFFFFFu, s, m);
    if (lane == 0) sd[wrp] = s;
    __syncthreads();
    if (tid == 0) {
        int best = 0;
        for (int k = 1; k < 3; ++k) {
            if (sd[k] > sd[best] || (sd[k] == sd[best] && cols[k] < cols[best])) best = k;
        }
        g_pdot[row] = sd[best];
        g_rdot[row] = sd[3 + best];
    }
}

// ---------------- final scalar loss ----------------
__global__ void loss_kernel(const float* __restrict__ adv,
                            const float* __restrict__ oldlp,
                            const int*   __restrict__ mask,
                            float* __restrict__ out) {
    __shared__ float sl[256], sm[256];
    int tid = threadIdx.x;
    float accl = 0.0f, accm = 0.0f;
    for (int r = tid; r < BT; r += 256) {
        int b = r / TT;
        float lse_p = logf(g_sum_pol[r]);
        float lse_r = logf(g_sum_ref[r]);
        float chosen_lp = g_pdot[r] - lse_p;
        float ref_lp    = g_rdot[r] - lse_r;

        float c1 = expf(chosen_lp - oldlp[r]);
        float c2 = fminf(fmaxf(c1, 1.0f - EPS_LO_C), 1.0f + EPS_HI_C);
        float a  = adv[b];
        float ptl = -fminf(c1 * a, c2 * a);

        float delta = ref_lp - chosen_lp;
        float kl = expf(delta) - delta - 1.0f;
        ptl += BETA_C * kl;

        float m = (float)mask[r];
        accl += ptl * m;
        accm += m;
    }
    sl[tid] = accl; sm[tid] = accm;
    __syncthreads();
    for (int s = 128; s > 0; s >>= 1) {
        if (tid < s) { sl[tid] += sl[tid + s]; sm[tid] += sm[tid + s]; }
        __syncthreads();
    }
    if (tid == 0) out[0] = sl[0] / fmaxf(sm[0], 1.0f);
}

// ---------------- launch ----------------
extern "C" void kernel_launch(void* const* d_in, const int* in_sizes, int n_in,
                              void* d_out, int out_size) {
    const float* x    = (const float*)d_in[0];
    const float* w    = (const float*)d_in[1];
    const float* rx   = (const float*)d_in[2];
    const float* rw   = (const float*)d_in[3];
    const float* adv  = (const float*)d_in[4];
    const float* oldl = (const float*)d_in[5];
    const int*   msk  = (const int*)d_in[6];
    float* out = (float*)d_out;

    float *sum_pol, *sum_ref;
    unsigned long long* cand;
    __half *xh, *wh, *rxh, *rwh;
    cudaGetSymbolAddress((void**)&sum_pol, g_sum_pol);
    cudaGetSymbolAddress((void**)&sum_ref, g_sum_ref);
    cudaGetSymbolAddress((void**)&cand,    g_cand);
    cudaGetSymbolAddress((void**)&xh,  g_xh);
    cudaGetSymbolAddress((void**)&wh,  g_wh);
    cudaGetSymbolAddress((void**)&rxh, g_rxh);
    cudaGetSymbolAddress((void**)&rwh, g_rwh);

    cudaFuncSetAttribute(gemm_mma, cudaFuncAttributeMaxDynamicSharedMemorySize, SMEM_DYN);

    init_kernel<<<(BT * CANDP + 255) / 256, 256>>>();

    const int nx16 = BT * HH / 16;
    const int nw16 = (int)((size_t)VV * HH / 16);

    convert_h<<<(nx16 + 255) / 256, 256>>>(x,  xh,  nx16);
    convert_h<<<(nw16 + 255) / 256, 256>>>(w,  wh,  nw16);
    convert_h<<<(nx16 + 255) / 256, 256>>>(rx, rxh, nx16);
    convert_h<<<(nw16 + 255) / 256, 256>>>(rw, rwh, nw16);

    dim3 grid(BT / BM, VV / BN);   // (16, 250)
    gemm_mma<<<grid, 256, SMEM_DYN>>>(xh,  wh,  sum_pol, cand, 1);
    gemm_mma<<<grid, 256, SMEM_DYN>>>(rxh, rwh, sum_ref, cand, 0);

    top3_kernel<<<BT, 256>>>();
    gather_pick<<<BT, 192>>>(x, w, rx, rw);
    loss_kernel<<<1, 256>>>(adv, oldl, msk, out);
}

// round 11
// speedup vs baseline: 1.0863x; 1.0863x over previous
#include <cuda_runtime.h>
#include <cuda_bf16.h>
#include <cuda_fp16.h>
#include <math.h>
#include <stdint.h>

// Problem constants
#define BB   4
#define TT   512
#define HH   2048
#define VV   32000
#define BT   (BB*TT)          // 2048 rows
#define NCTAY 250
#define CANDP 256             // padded stride for candidate table
#define BETA_C   0.1f
#define EPS_LO_C 0.2f
#define EPS_HI_C 0.2f

// GEMM tiling (legacy mma.sync path; tcgen05 not available on this target)
#define BM 128
#define BN 128
#define KC 32                  // K chunk in fp16 elems
#define NCHUNK (HH/KC)         // 64
#define NST 2                  // 2-stage: empirical optimum (NST=3 regressed twice)
#define PITCH 80               // conflict-free smem pitch for LDSM
#define A_OFF  0
#define BH_OFF 10240
#define STAGE_BYTES 20480
#define SMEM_DYN (NST*STAGE_BYTES)   // 40960 -> 2 CTAs/SM

// ---------------- scratch (static device globals; no allocations) ----------------
__device__ float              g_sum_pol[BT];
__device__ float              g_sum_ref[BT];
__device__ unsigned long long g_cand[BT*CANDP];   // per (row, ctaY) noisy max
__device__ uint4              g_top[BT];          // top-3 candidate cols per row (w unused)
__device__ float              g_pdot[BT];
__device__ float              g_rdot[BT];
__device__ __align__(1024) __half g_xh [BT*HH];
__device__ __align__(1024) __half g_wh [(size_t)VV*HH];
__device__ __align__(1024) __half g_rxh[BT*HH];
__device__ __align__(1024) __half g_rwh[(size_t)VV*HH];

// ---------------- PTX helpers ----------------
__device__ __forceinline__ uint32_t s2u(const void* p) {
    uint32_t a;
    asm("{ .reg .u64 t; cvta.to.shared.u64 t, %1; cvt.u32.u64 %0, t; }" : "=r"(a) : "l"(p));
    return a;
}
__device__ __forceinline__ void cpasync16(uint32_t s, const void* g) {
    asm volatile("cp.async.cg.shared.global [%0], [%1], 16;" :: "r"(s), "l"(g) : "memory");
}
__device__ __forceinline__ void cp_commit() {
    asm volatile("cp.async.commit_group;" ::: "memory");
}
template <int N>
__device__ __forceinline__ void cp_wait() {
    asm volatile("cp.async.wait_group %0;" :: "n"(N) : "memory");
}
__device__ __forceinline__ void ldsm4(uint32_t* r, uint32_t a) {
    asm volatile("ldmatrix.sync.aligned.m8n8.x4.shared.b16 {%0,%1,%2,%3}, [%4];"
                 : "=r"(r[0]), "=r"(r[1]), "=r"(r[2]), "=r"(r[3]) : "r"(a));
}
__device__ __forceinline__ void mma16816(float* d, const uint32_t* a, const uint32_t* b) {
    asm volatile(
        "mma.sync.aligned.m16n8k16.row.col.f32.f16.f16.f32 "
        "{%0,%1,%2,%3}, {%4,%5,%6,%7}, {%8,%9}, {%0,%1,%2,%3};"
        : "+f"(d[0]), "+f"(d[1]), "+f"(d[2]), "+f"(d[3])
        : "r"(a[0]), "r"(a[1]), "r"(a[2]), "r"(a[3]), "r"(b[0]), "r"(b[1]));
}
__device__ __forceinline__ unsigned fkey(float f) {
    unsigned u = __float_as_uint(f);
    return (u & 0x80000000u) ? ~u : (u | 0x80000000u);
}
// FMA-only exp
__device__ __forceinline__ float fexp(float x) {
    float t = x * 1.4426950408889634f;
    float r = rintf(t);
    float u = (t - r) * 0.6931471805599453f;
    float p = 8.3333333e-3f;
    p = fmaf(p, u, 4.1666667e-2f);
    p = fmaf(p, u, 1.6666667e-1f);
    p = fmaf(p, u, 0.5f);
    p = fmaf(p, u, 1.0f);
    p = fmaf(p, u, 1.0f);
    int e = (int)r;
    return p * __int_as_float((e + 127) << 23);
}

// ---------------- init ----------------
__global__ void init_kernel() {
    int i = blockIdx.x * blockDim.x + threadIdx.x;
    if (i < BT) { g_sum_pol[i] = 0.0f; g_sum_ref[i] = 0.0f; }
    if (i < BT * CANDP) g_cand[i] = 0ull;
}

// ---------------- fused convert: all 4 tensors, fp32 -> fp16, 8 elems/item ----------------
#define NXI (BT*HH/8)                       // 524288 items per activation tensor
#define NWI ((int)((size_t)VV*HH/8))        // 8192000 items per weight tensor
#define NTOT (2*NXI + 2*NWI)                // 17432576

__global__ void convert_all(const float* __restrict__ x,  const float* __restrict__ rx,
                            const float* __restrict__ w,  const float* __restrict__ rw,
                            __half* __restrict__ xh, __half* __restrict__ rxh,
                            __half* __restrict__ wh, __half* __restrict__ rwh) {
    int i = blockIdx.x * blockDim.x + threadIdx.x;
    if (i >= NTOT) return;
    const float* src;
    __half* dst;
    int j;
    if (i < NXI)            { src = x;  dst = xh;  j = i; }
    else if (i < 2*NXI)     { src = rx; dst = rxh; j = i - NXI; }
    else if (i < 2*NXI+NWI) { src = w;  dst = wh;  j = i - 2*NXI; }
    else                    { src = rw; dst = rwh; j = i - 2*NXI - NWI; }

    float4 v0 = ((const float4*)src)[2*(size_t)j];
    float4 v1 = ((const float4*)src)[2*(size_t)j+1];
    __half2 h[4];
    h[0] = __floats2half2_rn(v0.x, v0.y);
    h[1] = __floats2half2_rn(v0.z, v0.w);
    h[2] = __floats2half2_rn(v1.x, v1.y);
    h[3] = __floats2half2_rn(v1.z, v1.w);
    ((uint4*)dst)[(size_t)j] = *(uint4*)h;
}

// ---------------- single-fp16 tensor-core GEMM + fused softmax-stats ----------------
__global__ void __launch_bounds__(256, 2)
gemm_mma(const __half* __restrict__ Ah, const __half* __restrict__ Bh,
         float* __restrict__ sumexp, unsigned long long* __restrict__ cand,
         int do_max) {
    extern __shared__ char smem[];
    const uint32_t sb = s2u(smem);
    const int tid  = threadIdx.x;
    const int lane = tid & 31;
    const int wid  = tid >> 5;
    const int wm   = wid >> 2;
    const int wn   = wid & 3;
    const int m0 = blockIdx.x * BM;
    const int n0 = blockIdx.y * BN;

    float acc[4][4][4];
#pragma unroll
    for (int mt = 0; mt < 4; ++mt)
#pragma unroll
        for (int nt = 0; nt < 4; ++nt)
#pragma unroll
            for (int j = 0; j < 4; ++j) acc[mt][nt][j] = 0.0f;

    // cp.async: 1024 16B-chunks per stage = 4/thread (A:512, Bh:512)
    const int c0r = tid >> 2,  c0c = tid & 3;
    const int c1r = c0r + 64;

    auto load_stage = [&](int st, int k0) {
        uint32_t stb = sb + st * STAGE_BYTES;
        {
            uint32_t so = c0r * PITCH + c0c * 16;
            size_t ga = (size_t)(m0 + c0r) * HH + k0 + c0c * 8;
            size_t gb = (size_t)(n0 + c0r) * HH + k0 + c0c * 8;
            cpasync16(stb + A_OFF  + so, Ah + ga);
            cpasync16(stb + BH_OFF + so, Bh + gb);
        }
        {
            uint32_t so = c1r * PITCH + c0c * 16;
            size_t ga = (size_t)(m0 + c1r) * HH + k0 + c0c * 8;
            size_t gb = (size_t)(n0 + c1r) * HH + k0 + c0c * 8;
            cpasync16(stb + A_OFF  + so, Ah + ga);
            cpasync16(stb + BH_OFF + so, Bh + gb);
        }
    };

    load_stage(0, 0);
    cp_commit();

    const int arow_base = wm * 64 + (lane & 15);
    const int a_half    = (lane >> 4);
    const int brow_base = wn * 32 + ((lane >> 4) & 1) * 8 + (lane & 7);
    const int bksel     = (lane >> 3) & 1;

    for (int c = 0; c < NCHUNK; ++c) {
        if (c + 1 < NCHUNK) load_stage((c + 1) & 1, (c + 1) * KC);
        cp_commit();
        cp_wait<1>();
        __syncthreads();

        uint32_t stb = sb + (c & 1) * STAGE_BYTES;
#pragma unroll
        for (int ks = 0; ks < 2; ++ks) {
            uint32_t acol = (ks * 2 + a_half) * 16;
            uint32_t bcol = (ks * 2 + bksel) * 16;
            uint32_t ah[4][4], bh[2][4];
#pragma unroll
            for (int mt = 0; mt < 4; ++mt)
                ldsm4(ah[mt], stb + A_OFF + (uint32_t)(arow_base + mt * 16) * PITCH + acol);
#pragma unroll
            for (int p = 0; p < 2; ++p)
                ldsm4(bh[p], stb + BH_OFF + (uint32_t)(brow_base + p * 16) * PITCH + bcol);
#pragma unroll
            for (int mt = 0; mt < 4; ++mt)
#pragma unroll
                for (int nt = 0; nt < 4; ++nt)
                    mma16816(acc[mt][nt], ah[mt], &bh[nt >> 1][(nt & 1) * 2]);
        }
        __syncthreads();
    }

    // ---- epilogue: row-wise sum(exp); policy also records CTA-local row max ----
#pragma unroll
    for (int mt = 0; mt < 4; ++mt) {
#pragma unroll
        for (int half = 0; half < 2; ++half) {
            int row = m0 + wm * 64 + mt * 16 + (lane >> 2) + half * 8;
            float s = 0.0f;
            float vmax = -3.402823466e+38f;
            unsigned am = 0;
#pragma unroll
            for (int nt = 0; nt < 4; ++nt)
#pragma unroll
                for (int j = 0; j < 2; ++j) {
                    float v = acc[mt][nt][half * 2 + j];
                    s += fexp(v);
                    unsigned col = (unsigned)(n0 + wn * 32 + nt * 8 + (lane & 3) * 2 + j);
                    if (v > vmax) { vmax = v; am = col; }
                }
#pragma unroll
            for (int m = 1; m < 4; m <<= 1) {
                s += __shfl_xor_sync(0xFFFFFFFFu, s, m);
                float ov = __shfl_xor_sync(0xFFFFFFFFu, vmax, m);
                unsigned oa = __shfl_xor_sync(0xFFFFFFFFu, am, m);
                if (ov > vmax || (ov == vmax && oa < am)) { vmax = ov; am = oa; }
            }
            if ((lane & 3) == 0) {
                atomicAdd(&sumexp[row], s);
                if (do_max) {
                    unsigned long long p = ((unsigned long long)fkey(vmax) << 32)
                                         | (unsigned long long)(0xFFFFFFFFu - am);
                    atomicMax(&cand[(size_t)row * CANDP + blockIdx.y], p);
                }
            }
        }
    }
}

// ---------------- global top-3 candidates per row ----------------
__global__ void top3_kernel() {
    __shared__ unsigned long long sv[256];
    int row = blockIdx.x;
    int tid = threadIdx.x;
    unsigned long long v = (tid < NCTAY) ? g_cand[(size_t)row * CANDP + tid] : 0ull;
    sv[tid] = v; __syncthreads();
    for (int s = 128; s > 0; s >>= 1) {
        if (tid < s) sv[tid] = (sv[tid] > sv[tid + s]) ? sv[tid] : sv[tid + s];
        __syncthreads();
    }
    unsigned long long m1 = sv[0];
    __syncthreads();
    sv[tid] = (v == m1) ? 0ull : v; __syncthreads();
    for (int s = 128; s > 0; s >>= 1) {
        if (tid < s) sv[tid] = (sv[tid] > sv[tid + s]) ? sv[tid] : sv[tid + s];
        __syncthreads();
    }
    unsigned long long m2 = sv[0];
    __syncthreads();
    sv[tid] = (v == m1 || v == m2) ? 0ull : v; __syncthreads();
    for (int s = 128; s > 0; s >>= 1) {
        if (tid < s) sv[tid] = (sv[tid] > sv[tid + s]) ? sv[tid] : sv[tid + s];
        __syncthreads();
    }
    if (tid == 0) {
        unsigned long long m3 = sv[0];
        unsigned c1 = 0xFFFFFFFFu - (unsigned)(m1 & 0xFFFFFFFFull);
        unsigned c2 = (m2 != 0ull) ? (0xFFFFFFFFu - (unsigned)(m2 & 0xFFFFFFFFull)) : c1;
        unsigned c3 = (m3 != 0ull) ? (0xFFFFFFFFu - (unsigned)(m3 & 0xFFFFFFFFull)) : c1;
        g_top[row] = make_uint4(c1, c2, c3, 0u);
    }
}

// ---------------- exact fp32 dots for top-3, pick true argmax ----------------
__global__ void gather_pick(const float* __restrict__ x, const float* __restrict__ w,
                            const float* __restrict__ rx, const float* __restrict__ rw) {
    __shared__ float sd[6];
    int row = blockIdx.x;
    int tid = threadIdx.x;
    int wrp = tid >> 5;         // 0..5: (model, cand) = (wrp/3, wrp%3)
    int lane = tid & 31;
    uint4 t = g_top[row];
    unsigned cols[3] = { t.x, t.y, t.z };
    unsigned col = cols[wrp % 3];
    const float* a = (wrp < 3) ? (x + (size_t)row * HH) : (rx + (size_t)row * HH);
    const float* b = (wrp < 3) ? (w + (size_t)col * HH) : (rw + (size_t)col * HH);
    float s = 0.0f;
    for (int h = lane; h < HH; h += 32) s = fmaf(a[h], b[h], s);
#pragma unroll
    for (int m = 16; m >= 1; m >>= 1) s += __shfl_xor_sync(0xFFFFFFFFu, s, m);
    if (lane == 0) sd[wrp] = s;
    __syncthreads();
    if (tid == 0) {
        int best = 0;
        for (int k = 1; k < 3; ++k) {
            if (sd[k] > sd[best] || (sd[k] == sd[best] && cols[k] < cols[best])) best = k;
        }
        g_pdot[row] = sd[best];
        g_rdot[row] = sd[3 + best];
    }
}

// ---------------- final scalar loss ----------------
__global__ void loss_kernel(const float* __restrict__ adv,
                            const float* __restrict__ oldlp,
                            const int*   __restrict__ mask,
                            float* __restrict__ out) {
    __shared__ float sl[256], sm[256];
    int tid = threadIdx.x;
    float accl = 0.0f, accm = 0.0f;
    for (int r = tid; r < BT; r += 256) {
        int b = r / TT;
        float lse_p = logf(g_sum_pol[r]);
        float lse_r = logf(g_sum_ref[r]);
        float chosen_lp = g_pdot[r] - lse_p;
        float ref_lp    = g_rdot[r] - lse_r;

        float c1 = expf(chosen_lp - oldlp[r]);
        float c2 = fminf(fmaxf(c1, 1.0f - EPS_LO_C), 1.0f + EPS_HI_C);
        float a  = adv[b];
        float ptl = -fminf(c1 * a, c2 * a);

        float delta = ref_lp - chosen_lp;
        float kl = expf(delta) - delta - 1.0f;
        ptl += BETA_C * kl;

        float m = (float)mask[r];
        accl += ptl * m;
        accm += m;
    }
    sl[tid] = accl; sm[tid] = accm;
    __syncthreads();
    for (int s = 128; s > 0; s >>= 1) {
        if (tid < s) { sl[tid] += sl[tid + s]; sm[tid] += sm[tid + s]; }
        __syncthreads();
    }
    if (tid == 0) out[0] = sl[0] / fmaxf(sm[0], 1.0f);
}

// ---------------- launch ----------------
extern "C" void kernel_launch(void* const* d_in, const int* in_sizes, int n_in,
                              void* d_out, int out_size) {
    const float* x    = (const float*)d_in[0];
    const float* w    = (const float*)d_in[1];
    const float* rx   = (const float*)d_in[2];
    const float* rw   = (const float*)d_in[3];
    const float* adv  = (const float*)d_in[4];
    const float* oldl = (const float*)d_in[5];
    const int*   msk  = (const int*)d_in[6];
    float* out = (float*)d_out;

    float *sum_pol, *sum_ref;
    unsigned long long* cand;
    __half *xh, *wh, *rxh, *rwh;
    cudaGetSymbolAddress((void**)&sum_pol, g_sum_pol);
    cudaGetSymbolAddress((void**)&sum_ref, g_sum_ref);
    cudaGetSymbolAddress((void**)&cand,    g_cand);
    cudaGetSymbolAddress((void**)&xh,  g_xh);
    cudaGetSymbolAddress((void**)&wh,  g_wh);
    cudaGetSymbolAddress((void**)&rxh, g_rxh);
    cudaGetSymbolAddress((void**)&rwh, g_rwh);

    cudaFuncSetAttribute(gemm_mma, cudaFuncAttributeMaxDynamicSharedMemorySize, SMEM_DYN);

    init_kernel<<<(BT * CANDP + 255) / 256, 256>>>();

    convert_all<<<(NTOT + 255) / 256, 256>>>(x, rx, w, rw, xh, rxh, wh, rwh);

    dim3 grid(BT / BM, VV / BN);   // (16, 250)
    gemm_mma<<<grid, 256, SMEM_DYN>>>(xh,  wh,  sum_pol, cand, 1);
    gemm_mma<<<grid, 256, SMEM_DYN>>>(rxh, rwh, sum_ref, cand, 0);

    top3_kernel<<<BT, 256>>>();
    gather_pick<<<BT, 192>>>(x, w, rx, rw);
    loss_kernel<<<1, 256>>>(adv, oldl, msk, out);
}

// round 12
// speedup vs baseline: 1.1788x; 1.0851x over previous
#include <cuda_runtime.h>
#include <cuda_bf16.h>
#include <cuda_fp16.h>
#include <math.h>
#include <stdint.h>

// Problem constants
#define BB   4
#define TT   512
#define HH   2048
#define VV   32000
#define BT   (BB*TT)          // 2048 rows
#define NCTAY 250
#define CANDP 256             // padded stride for candidate table
#define BETA_C   0.1f
#define EPS_LO_C 0.2f
#define EPS_HI_C 0.2f

// GEMM tiling (legacy mma.sync path; tcgen05 not available on this target)
#define BM 128
#define BN 128
#define KC 64                  // K chunk in fp16 elems (doubled: halves barrier convoys)
#define NKS (KC/16)            // 4 ks-steps per chunk
#define NCHUNK (HH/KC)         // 32
#define NST 2                  // 2-stage: empirical optimum (NST=3 regressed twice)
#define PITCH 144              // 128B data + 16B pad; conflict-free for LDSM
#define A_OFF  0
#define BH_OFF 18432
#define STAGE_BYTES 36864
#define SMEM_DYN (NST*STAGE_BYTES)   // 73728 -> 2 CTAs/SM

// ---------------- scratch (static device globals; no allocations) ----------------
__device__ float              g_sum_pol[BT];
__device__ float              g_sum_ref[BT];
__device__ unsigned long long g_cand[BT*CANDP];   // per (row, ctaY) noisy max
__device__ uint4              g_top[BT];          // top-3 candidate cols per row (w unused)
__device__ float              g_pdot[BT];
__device__ float              g_rdot[BT];
__device__ __align__(1024) __half g_xh [BT*HH];
__device__ __align__(1024) __half g_wh [(size_t)VV*HH];
__device__ __align__(1024) __half g_rxh[BT*HH];
__device__ __align__(1024) __half g_rwh[(size_t)VV*HH];

// ---------------- PTX helpers ----------------
__device__ __forceinline__ uint32_t s2u(const void* p) {
    uint32_t a;
    asm("{ .reg .u64 t; cvta.to.shared.u64 t, %1; cvt.u32.u64 %0, t; }" : "=r"(a) : "l"(p));
    return a;
}
__device__ __forceinline__ void cpasync16(uint32_t s, const void* g) {
    asm volatile("cp.async.cg.shared.global [%0], [%1], 16;" :: "r"(s), "l"(g) : "memory");
}
__device__ __forceinline__ void cp_commit() {
    asm volatile("cp.async.commit_group;" ::: "memory");
}
template <int N>
__device__ __forceinline__ void cp_wait() {
    asm volatile("cp.async.wait_group %0;" :: "n"(N) : "memory");
}
__device__ __forceinline__ void ldsm4(uint32_t* r, uint32_t a) {
    asm volatile("ldmatrix.sync.aligned.m8n8.x4.shared.b16 {%0,%1,%2,%3}, [%4];"
                 : "=r"(r[0]), "=r"(r[1]), "=r"(r[2]), "=r"(r[3]) : "r"(a));
}
__device__ __forceinline__ void mma16816(float* d, const uint32_t* a, const uint32_t* b) {
    asm volatile(
        "mma.sync.aligned.m16n8k16.row.col.f32.f16.f16.f32 "
        "{%0,%1,%2,%3}, {%4,%5,%6,%7}, {%8,%9}, {%0,%1,%2,%3};"
        : "+f"(d[0]), "+f"(d[1]), "+f"(d[2]), "+f"(d[3])
        : "r"(a[0]), "r"(a[1]), "r"(a[2]), "r"(a[3]), "r"(b[0]), "r"(b[1]));
}
__device__ __forceinline__ unsigned fkey(float f) {
    unsigned u = __float_as_uint(f);
    return (u & 0x80000000u) ? ~u : (u | 0x80000000u);
}
// FMA-only exp
__device__ __forceinline__ float fexp(float x) {
    float t = x * 1.4426950408889634f;
    float r = rintf(t);
    float u = (t - r) * 0.6931471805599453f;
    float p = 8.3333333e-3f;
    p = fmaf(p, u, 4.1666667e-2f);
    p = fmaf(p, u, 1.6666667e-1f);
    p = fmaf(p, u, 0.5f);
    p = fmaf(p, u, 1.0f);
    p = fmaf(p, u, 1.0f);
    int e = (int)r;
    return p * __int_as_float((e + 127) << 23);
}

// ---------------- init ----------------
__global__ void init_kernel() {
    int i = blockIdx.x * blockDim.x + threadIdx.x;
    if (i < BT) { g_sum_pol[i] = 0.0f; g_sum_ref[i] = 0.0f; }
    if (i < BT * CANDP) g_cand[i] = 0ull;
}

// ---------------- fused convert: all 4 tensors, fp32 -> fp16, 8 elems/item ----------------
#define NXI (BT*HH/8)                       // 524288 items per activation tensor
#define NWI ((int)((size_t)VV*HH/8))        // 8192000 items per weight tensor
#define NTOT (2*NXI + 2*NWI)                // 17432576

__global__ void convert_all(const float* __restrict__ x,  const float* __restrict__ rx,
                            const float* __restrict__ w,  const float* __restrict__ rw,
                            __half* __restrict__ xh, __half* __restrict__ rxh,
                            __half* __restrict__ wh, __half* __restrict__ rwh) {
    int i = blockIdx.x * blockDim.x + threadIdx.x;
    if (i >= NTOT) return;
    const float* src;
    __half* dst;
    int j;
    if (i < NXI)            { src = x;  dst = xh;  j = i; }
    else if (i < 2*NXI)     { src = rx; dst = rxh; j = i - NXI; }
    else if (i < 2*NXI+NWI) { src = w;  dst = wh;  j = i - 2*NXI; }
    else                    { src = rw; dst = rwh; j = i - 2*NXI - NWI; }

    float4 v0 = ((const float4*)src)[2*(size_t)j];
    float4 v1 = ((const float4*)src)[2*(size_t)j+1];
    __half2 h[4];
    h[0] = __floats2half2_rn(v0.x, v0.y);
    h[1] = __floats2half2_rn(v0.z, v0.w);
    h[2] = __floats2half2_rn(v1.x, v1.y);
    h[3] = __floats2half2_rn(v1.z, v1.w);
    ((uint4*)dst)[(size_t)j] = *(uint4*)h;
}

// ---------------- single-fp16 tensor-core GEMM + fused softmax-stats ----------------
__global__ void __launch_bounds__(256, 2)
gemm_mma(const __half* __restrict__ Ah, const __half* __restrict__ Bh,
         float* __restrict__ sumexp, unsigned long long* __restrict__ cand,
         int do_max) {
    extern __shared__ char smem[];
    const uint32_t sb = s2u(smem);
    const int tid  = threadIdx.x;
    const int lane = tid & 31;
    const int wid  = tid >> 5;
    const int wm   = wid >> 2;
    const int wn   = wid & 3;
    const int m0 = blockIdx.x * BM;
    const int n0 = blockIdx.y * BN;

    float acc[4][4][4];
#pragma unroll
    for (int mt = 0; mt < 4; ++mt)
#pragma unroll
        for (int nt = 0; nt < 4; ++nt)
#pragma unroll
            for (int j = 0; j < 4; ++j) acc[mt][nt][j] = 0.0f;

    // cp.async: per matrix 128 rows x 128B = 1024 16B-chunks -> 4/thread; 8 total
    auto load_stage = [&](int st, int k0) {
        uint32_t stb = sb + st * STAGE_BYTES;
#pragma unroll
        for (int it = 0; it < 4; ++it) {
            int id  = tid + it * 256;          // 0..1023
            int row = id >> 3;                  // 0..127
            int cq  = id & 7;                   // 0..7 (16B chunk in row)
            uint32_t so = (uint32_t)row * PITCH + (uint32_t)cq * 16;
            size_t ga = (size_t)(m0 + row) * HH + k0 + cq * 8;
            size_t gb = (size_t)(n0 + row) * HH + k0 + cq * 8;
            cpasync16(stb + A_OFF  + so, Ah + ga);
            cpasync16(stb + BH_OFF + so, Bh + gb);
        }
    };

    load_stage(0, 0);
    cp_commit();

    const int arow_base = wm * 64 + (lane & 15);
    const int a_half    = (lane >> 4);
    const int brow_base = wn * 32 + ((lane >> 4) & 1) * 8 + (lane & 7);
    const int bksel     = (lane >> 3) & 1;

    for (int c = 0; c < NCHUNK; ++c) {
        if (c + 1 < NCHUNK) load_stage((c + 1) & 1, (c + 1) * KC);
        cp_commit();
        cp_wait<1>();
        __syncthreads();

        uint32_t stb = sb + (c & 1) * STAGE_BYTES;
#pragma unroll
        for (int ks = 0; ks < NKS; ++ks) {
            uint32_t acol = (ks * 2 + a_half) * 16;
            uint32_t bcol = (ks * 2 + bksel) * 16;
            uint32_t ah[4][4], bh[2][4];
#pragma unroll
            for (int mt = 0; mt < 4; ++mt)
                ldsm4(ah[mt], stb + A_OFF + (uint32_t)(arow_base + mt * 16) * PITCH + acol);
#pragma unroll
            for (int p = 0; p < 2; ++p)
                ldsm4(bh[p], stb + BH_OFF + (uint32_t)(brow_base + p * 16) * PITCH + bcol);
#pragma unroll
            for (int mt = 0; mt < 4; ++mt)
#pragma unroll
                for (int nt = 0; nt < 4; ++nt)
                    mma16816(acc[mt][nt], ah[mt], &bh[nt >> 1][(nt & 1) * 2]);
        }
        __syncthreads();
    }

    // ---- epilogue: row-wise sum(exp); policy also records CTA-local row max ----
#pragma unroll
    for (int mt = 0; mt < 4; ++mt) {
#pragma unroll
        for (int half = 0; half < 2; ++half) {
            int row = m0 + wm * 64 + mt * 16 + (lane >> 2) + half * 8;
            float s = 0.0f;
            float vmax = -3.402823466e+38f;
            unsigned am = 0;
#pragma unroll
            for (int nt = 0; nt < 4; ++nt)
#pragma unroll
                for (int j = 0; j < 2; ++j) {
                    float v = acc[mt][nt][half * 2 + j];
                    s += fexp(v);
                    unsigned col = (unsigned)(n0 + wn * 32 + nt * 8 + (lane & 3) * 2 + j);
                    if (v > vmax) { vmax = v; am = col; }
                }
#pragma unroll
            for (int m = 1; m < 4; m <<= 1) {
                s += __shfl_xor_sync(0xFFFFFFFFu, s, m);
                float ov = __shfl_xor_sync(0xFFFFFFFFu, vmax, m);
                unsigned oa = __shfl_xor_sync(0xFFFFFFFFu, am, m);
                if (ov > vmax || (ov == vmax && oa < am)) { vmax = ov; am = oa; }
            }
            if ((lane & 3) == 0) {
                atomicAdd(&sumexp[row], s);
                if (do_max) {
                    unsigned long long p = ((unsigned long long)fkey(vmax) << 32)
                                         | (unsigned long long)(0xFFFFFFFFu - am);
                    atomicMax(&cand[(size_t)row * CANDP + blockIdx.y], p);
                }
            }
        }
    }
}

// ---------------- global top-3 candidates per row ----------------
__global__ void top3_kernel() {
    __shared__ unsigned long long sv[256];
    int row = blockIdx.x;
    int tid = threadIdx.x;
    unsigned long long v = (tid < NCTAY) ? g_cand[(size_t)row * CANDP + tid] : 0ull;
    sv[tid] = v; __syncthreads();
    for (int s = 128; s > 0; s >>= 1) {
        if (tid < s) sv[tid] = (sv[tid] > sv[tid + s]) ? sv[tid] : sv[tid + s];
        __syncthreads();
    }
    unsigned long long m1 = sv[0];
    __syncthreads();
    sv[tid] = (v == m1) ? 0ull : v; __syncthreads();
    for (int s = 128; s > 0; s >>= 1) {
        if (tid < s) sv[tid] = (sv[tid] > sv[tid + s]) ? sv[tid] : sv[tid + s];
        __syncthreads();
    }
    unsigned long long m2 = sv[0];
    __syncthreads();
    sv[tid] = (v == m1 || v == m2) ? 0ull : v; __syncthreads();
    for (int s = 128; s > 0; s >>= 1) {
        if (tid < s) sv[tid] = (sv[tid] > sv[tid + s]) ? sv[tid] : sv[tid + s];
        __syncthreads();
    }
    if (tid == 0) {
        unsigned long long m3 = sv[0];
        unsigned c1 = 0xFFFFFFFFu - (unsigned)(m1 & 0xFFFFFFFFull);
        unsigned c2 = (m2 != 0ull) ? (0xFFFFFFFFu - (unsigned)(m2 & 0xFFFFFFFFull)) : c1;
        unsigned c3 = (m3 != 0ull) ? (0xFFFFFFFFu - (unsigned)(m3 & 0xFFFFFFFFull)) : c1;
        g_top[row] = make_uint4(c1, c2, c3, 0u);
    }
}

// ---------------- exact fp32 dots for top-3, pick true argmax ----------------
__global__ void gather_pick(const float* __restrict__ x, const float* __restrict__ w,
                            const float* __restrict__ rx, const float* __restrict__ rw) {
    __shared__ float sd[6];
    int row = blockIdx.x;
    int tid = threadIdx.x;
    int wrp = tid >> 5;         // 0..5: (model, cand) = (wrp/3, wrp%3)
    int lane = tid & 31;
    uint4 t = g_top[row];
    unsigned cols[3] = { t.x, t.y, t.z };
    unsigned col = cols[wrp % 3];
    const float* a = (wrp < 3) ? (x + (size_t)row * HH) : (rx + (size_t)row * HH);
    const float* b = (wrp < 3) ? (w + (size_t)col * HH) : (rw + (size_t)col * HH);
    float s = 0.0f;
    for (int h = lane; h < HH; h += 32) s = fmaf(a[h], b[h], s);
#pragma unroll
    for (int m = 16; m >= 1; m >>= 1) s += __shfl_xor_sync(0xFFFFFFFFu, s, m);
    if (lane == 0) sd[wrp] = s;
    __syncthreads();
    if (tid == 0) {
        int best = 0;
        for (int k = 1; k < 3; ++k) {
            if (sd[k] > sd[best] || (sd[k] == sd[best] && cols[k] < cols[best])) best = k;
        }
        g_pdot[row] = sd[best];
        g_rdot[row] = sd[3 + best];
    }
}

// ---------------- final scalar loss ----------------
__global__ void loss_kernel(const float* __restrict__ adv,
                            const float* __restrict__ oldlp,
                            const int*   __restrict__ mask,
                            float* __restrict__ out) {
    __shared__ float sl[256], sm[256];
    int tid = threadIdx.x;
    float accl = 0.0f, accm = 0.0f;
    for (int r = tid; r < BT; r += 256) {
        int b = r / TT;
        float lse_p = logf(g_sum_pol[r]);
        float lse_r = logf(g_sum_ref[r]);
        float chosen_lp = g_pdot[r] - lse_p;
        float ref_lp    = g_rdot[r] - lse_r;

        float c1 = expf(chosen_lp - oldlp[r]);
        float c2 = fminf(fmaxf(c1, 1.0f - EPS_LO_C), 1.0f + EPS_HI_C);
        float a  = adv[b];
        float ptl = -fminf(c1 * a, c2 * a);

        float delta = ref_lp - chosen_lp;
        float kl = expf(delta) - delta - 1.0f;
        ptl += BETA_C * kl;

        float m = (float)mask[r];
        accl += ptl * m;
        accm += m;
    }
    sl[tid] = accl; sm[tid] = accm;
    __syncthreads();
    for (int s = 128; s > 0; s >>= 1) {
        if (tid < s) { sl[tid] += sl[tid + s]; sm[tid] += sm[tid + s]; }
        __syncthreads();
    }
    if (tid == 0) out[0] = sl[0] / fmaxf(sm[0], 1.0f);
}

// ---------------- launch ----------------
extern "C" void kernel_launch(void* const* d_in, const int* in_sizes, int n_in,
                              void* d_out, int out_size) {
    const float* x    = (const float*)d_in[0];
    const float* w    = (const float*)d_in[1];
    const float* rx   = (const float*)d_in[2];
    const float* rw   = (const float*)d_in[3];
    const float* adv  = (const float*)d_in[4];
    const float* oldl = (const float*)d_in[5];
    const int*   msk  = (const int*)d_in[6];
    float* out = (float*)d_out;

    float *sum_pol, *sum_ref;
    unsigned long long* cand;
    __half *xh, *wh, *rxh, *rwh;
    cudaGetSymbolAddress((void**)&sum_pol, g_sum_pol);
    cudaGetSymbolAddress((void**)&sum_ref, g_sum_ref);
    cudaGetSymbolAddress((void**)&cand,    g_cand);
    cudaGetSymbolAddress((void**)&xh,  g_xh);
    cudaGetSymbolAddress((void**)&wh,  g_wh);
    cudaGetSymbolAddress((void**)&rxh, g_rxh);
    cudaGetSymbolAddress((void**)&rwh, g_rwh);

    cudaFuncSetAttribute(gemm_mma, cudaFuncAttributeMaxDynamicSharedMemorySize, SMEM_DYN);

    init_kernel<<<(BT * CANDP + 255) / 256, 256>>>();

    convert_all<<<(NTOT + 255) / 256, 256>>>(x, rx, w, rw, xh, rxh, wh, rwh);

    dim3 grid(BT / BM, VV / BN);   // (16, 250)
    gemm_mma<<<grid, 256, SMEM_DYN>>>(xh,  wh,  sum_pol, cand, 1);
    gemm_mma<<<grid, 256, SMEM_DYN>>>(rxh, rwh, sum_ref, cand, 0);

    top3_kernel<<<BT, 256>>>();
    gather_pick<<<BT, 192>>>(x, w, rx, rw);
    loss_kernel<<<1, 256>>>(adv, oldl, msk, out);
}

// round 13
// speedup vs baseline: 1.2562x; 1.0656x over previous
#include <cuda_runtime.h>
#include <cuda_bf16.h>
#include <cuda_fp16.h>
#include <math.h>
#include <stdint.h>

// Problem constants
#define BB   4
#define TT   512
#define HH   2048
#define VV   32000
#define BT   (BB*TT)          // 2048 rows
#define NCTAY 500
#define CANDP 512             // padded stride for candidate table
#define BETA_C   0.1f
#define EPS_LO_C 0.2f
#define EPS_HI_C 0.2f

// GEMM tiling (legacy mma.sync path; tcgen05 not available on this target)
#define BM 128
#define BN 64                  // narrow CTA -> 4 CTAs/SM, 4 barrier domains
#define KC 64                  // K chunk in fp16 elems
#define NKS (KC/16)            // 4 ks-steps per chunk
#define NCHUNK (HH/KC)         // 32
#define NST 2                  // 2-stage: empirical optimum
#define PITCH 144              // 128B data + 16B pad; conflict-free for LDSM
#define A_OFF  0
#define BH_OFF 18432           // 128 rows * 144
#define STAGE_BYTES 27648      // + 64 rows * 144
#define SMEM_DYN (NST*STAGE_BYTES)   // 55296 -> 4 CTAs/SM
#define GT 128                 // threads per CTA

// ---------------- scratch (static device globals; no allocations) ----------------
__device__ float              g_sum_pol[BT];
__device__ float              g_sum_ref[BT];
__device__ unsigned long long g_cand[BT*CANDP];   // per (row, ctaY) noisy max
__device__ uint4              g_top[BT];          // top-3 candidate cols per row (w unused)
__device__ float              g_pdot[BT];
__device__ float              g_rdot[BT];
__device__ __align__(1024) __half g_xh [BT*HH];
__device__ __align__(1024) __half g_wh [(size_t)VV*HH];
__device__ __align__(1024) __half g_rxh[BT*HH];
__device__ __align__(1024) __half g_rwh[(size_t)VV*HH];

// ---------------- PTX helpers ----------------
__device__ __forceinline__ uint32_t s2u(const void* p) {
    uint32_t a;
    asm("{ .reg .u64 t; cvta.to.shared.u64 t, %1; cvt.u32.u64 %0, t; }" : "=r"(a) : "l"(p));
    return a;
}
__device__ __forceinline__ void cpasync16(uint32_t s, const void* g) {
    asm volatile("cp.async.cg.shared.global [%0], [%1], 16;" :: "r"(s), "l"(g) : "memory");
}
__device__ __forceinline__ void cp_commit() {
    asm volatile("cp.async.commit_group;" ::: "memory");
}
template <int N>
__device__ __forceinline__ void cp_wait() {
    asm volatile("cp.async.wait_group %0;" :: "n"(N) : "memory");
}
__device__ __forceinline__ void ldsm4(uint32_t* r, uint32_t a) {
    asm volatile("ldmatrix.sync.aligned.m8n8.x4.shared.b16 {%0,%1,%2,%3}, [%4];"
                 : "=r"(r[0]), "=r"(r[1]), "=r"(r[2]), "=r"(r[3]) : "r"(a));
}
__device__ __forceinline__ void mma16816(float* d, const uint32_t* a, const uint32_t* b) {
    asm volatile(
        "mma.sync.aligned.m16n8k16.row.col.f32.f16.f16.f32 "
        "{%0,%1,%2,%3}, {%4,%5,%6,%7}, {%8,%9}, {%0,%1,%2,%3};"
        : "+f"(d[0]), "+f"(d[1]), "+f"(d[2]), "+f"(d[3])
        : "r"(a[0]), "r"(a[1]), "r"(a[2]), "r"(a[3]), "r"(b[0]), "r"(b[1]));
}
__device__ __forceinline__ unsigned fkey(float f) {
    unsigned u = __float_as_uint(f);
    return (u & 0x80000000u) ? ~u : (u | 0x80000000u);
}
// FMA-only exp
__device__ __forceinline__ float fexp(float x) {
    float t = x * 1.4426950408889634f;
    float r = rintf(t);
    float u = (t - r) * 0.6931471805599453f;
    float p = 8.3333333e-3f;
    p = fmaf(p, u, 4.1666667e-2f);
    p = fmaf(p, u, 1.6666667e-1f);
    p = fmaf(p, u, 0.5f);
    p = fmaf(p, u, 1.0f);
    p = fmaf(p, u, 1.0f);
    int e = (int)r;
    return p * __int_as_float((e + 127) << 23);
}

// ---------------- init ----------------
__global__ void init_kernel() {
    int i = blockIdx.x * blockDim.x + threadIdx.x;
    if (i < BT) { g_sum_pol[i] = 0.0f; g_sum_ref[i] = 0.0f; }
    if (i < BT * CANDP) g_cand[i] = 0ull;
}

// ---------------- fused convert: all 4 tensors, fp32 -> fp16, 8 elems/item ----------------
#define NXI (BT*HH/8)                       // 524288 items per activation tensor
#define NWI ((int)((size_t)VV*HH/8))        // 8192000 items per weight tensor
#define NTOT (2*NXI + 2*NWI)                // 17432576

__global__ void convert_all(const float* __restrict__ x,  const float* __restrict__ rx,
                            const float* __restrict__ w,  const float* __restrict__ rw,
                            __half* __restrict__ xh, __half* __restrict__ rxh,
                            __half* __restrict__ wh, __half* __restrict__ rwh) {
    int i = blockIdx.x * blockDim.x + threadIdx.x;
    if (i >= NTOT) return;
    const float* src;
    __half* dst;
    int j;
    if (i < NXI)            { src = x;  dst = xh;  j = i; }
    else if (i < 2*NXI)     { src = rx; dst = rxh; j = i - NXI; }
    else if (i < 2*NXI+NWI) { src = w;  dst = wh;  j = i - 2*NXI; }
    else                    { src = rw; dst = rwh; j = i - 2*NXI - NWI; }

    float4 v0 = ((const float4*)src)[2*(size_t)j];
    float4 v1 = ((const float4*)src)[2*(size_t)j+1];
    __half2 h[4];
    h[0] = __floats2half2_rn(v0.x, v0.y);
    h[1] = __floats2half2_rn(v0.z, v0.w);
    h[2] = __floats2half2_rn(v1.x, v1.y);
    h[3] = __floats2half2_rn(v1.z, v1.w);
    ((uint4*)dst)[(size_t)j] = *(uint4*)h;
}

// ---------------- single-fp16 tensor-core GEMM + fused softmax-stats ----------------
__global__ void __launch_bounds__(GT, 4)
gemm_mma(const __half* __restrict__ Ah, const __half* __restrict__ Bh,
         float* __restrict__ sumexp, unsigned long long* __restrict__ cand,
         int do_max) {
    extern __shared__ char smem[];
    const uint32_t sb = s2u(smem);
    const int tid  = threadIdx.x;
    const int lane = tid & 31;
    const int wid  = tid >> 5;         // 0..3
    const int wm   = wid >> 1;          // 0..1 (64-row slab)
    const int wn   = wid & 1;           // 0..1 (32-col slab)
    const int m0 = blockIdx.x * BM;
    const int n0 = blockIdx.y * BN;

    float acc[4][4][4];
#pragma unroll
    for (int mt = 0; mt < 4; ++mt)
#pragma unroll
        for (int nt = 0; nt < 4; ++nt)
#pragma unroll
            for (int j = 0; j < 4; ++j) acc[mt][nt][j] = 0.0f;

    // cp.async per stage: A 128 rows x 8 chunks = 1024, B 64 x 8 = 512 -> 12/thread
    auto load_stage = [&](int st, int k0) {
        uint32_t stb = sb + st * STAGE_BYTES;
#pragma unroll
        for (int it = 0; it < 8; ++it) {           // A chunks: ids 0..1023
            int id  = tid + it * GT;
            int row = id >> 3;
            int cq  = id & 7;
            uint32_t so = (uint32_t)row * PITCH + (uint32_t)cq * 16;
            cpasync16(stb + A_OFF + so, Ah + (size_t)(m0 + row) * HH + k0 + cq * 8);
        }
#pragma unroll
        for (int it = 0; it < 4; ++it) {           // B chunks: ids 0..511
            int id  = tid + it * GT;
            int row = id >> 3;
            int cq  = id & 7;
            uint32_t so = (uint32_t)row * PITCH + (uint32_t)cq * 16;
            cpasync16(stb + BH_OFF + so, Bh + (size_t)(n0 + row) * HH + k0 + cq * 8);
        }
    };

    load_stage(0, 0);
    cp_commit();

    const int arow_base = wm * 64 + (lane & 15);
    const int a_half    = (lane >> 4);
    const int brow_base = wn * 32 + ((lane >> 4) & 1) * 8 + (lane & 7);
    const int bksel     = (lane >> 3) & 1;

    for (int c = 0; c < NCHUNK; ++c) {
        if (c + 1 < NCHUNK) load_stage((c + 1) & 1, (c + 1) * KC);
        cp_commit();
        cp_wait<1>();
        __syncthreads();

        uint32_t stb = sb + (c & 1) * STAGE_BYTES;
#pragma unroll
        for (int ks = 0; ks < NKS; ++ks) {
            uint32_t acol = (ks * 2 + a_half) * 16;
            uint32_t bcol = (ks * 2 + bksel) * 16;
            uint32_t ah[4][4], bh[2][4];
#pragma unroll
            for (int mt = 0; mt < 4; ++mt)
                ldsm4(ah[mt], stb + A_OFF + (uint32_t)(arow_base + mt * 16) * PITCH + acol);
#pragma unroll
            for (int p = 0; p < 2; ++p)
                ldsm4(bh[p], stb + BH_OFF + (uint32_t)(brow_base + p * 16) * PITCH + bcol);
#pragma unroll
            for (int mt = 0; mt < 4; ++mt)
#pragma unroll
                for (int nt = 0; nt < 4; ++nt)
                    mma16816(acc[mt][nt], ah[mt], &bh[nt >> 1][(nt & 1) * 2]);
        }
        __syncthreads();
    }

    // ---- epilogue: row-wise sum(exp); policy also records CTA-local row max ----
#pragma unroll
    for (int mt = 0; mt < 4; ++mt) {
#pragma unroll
        for (int half = 0; half < 2; ++half) {
            int row = m0 + wm * 64 + mt * 16 + (lane >> 2) + half * 8;
            float s = 0.0f;
            float vmax = -3.402823466e+38f;
            unsigned am = 0;
#pragma unroll
            for (int nt = 0; nt < 4; ++nt)
#pragma unroll
                for (int j = 0; j < 2; ++j) {
                    float v = acc[mt][nt][half * 2 + j];
                    s += fexp(v);
                    unsigned col = (unsigned)(n0 + wn * 32 + nt * 8 + (lane & 3) * 2 + j);
                    if (v > vmax) { vmax = v; am = col; }
                }
#pragma unroll
            for (int m = 1; m < 4; m <<= 1) {
                s += __shfl_xor_sync(0xFFFFFFFFu, s, m);
                float ov = __shfl_xor_sync(0xFFFFFFFFu, vmax, m);
                unsigned oa = __shfl_xor_sync(0xFFFFFFFFu, am, m);
                if (ov > vmax || (ov == vmax && oa < am)) { vmax = ov; am = oa; }
            }
            if ((lane & 3) == 0) {
                atomicAdd(&sumexp[row], s);
                if (do_max) {
                    unsigned long long p = ((unsigned long long)fkey(vmax) << 32)
                                         | (unsigned long long)(0xFFFFFFFFu - am);
                    atomicMax(&cand[(size_t)row * CANDP + blockIdx.y], p);
                }
            }
        }
    }
}

// ---------------- global top-3 candidates per row ----------------
__global__ void top3_kernel() {
    __shared__ unsigned long long sv[512];
    int row = blockIdx.x;
    int tid = threadIdx.x;
    unsigned long long v = (tid < NCTAY) ? g_cand[(size_t)row * CANDP + tid] : 0ull;
    sv[tid] = v; __syncthreads();
    for (int s = 256; s > 0; s >>= 1) {
        if (tid < s) sv[tid] = (sv[tid] > sv[tid + s]) ? sv[tid] : sv[tid + s];
        __syncthreads();
    }
    unsigned long long m1 = sv[0];
    __syncthreads();
    sv[tid] = (v == m1) ? 0ull : v; __syncthreads();
    for (int s = 256; s > 0; s >>= 1) {
        if (tid < s) sv[tid] = (sv[tid] > sv[tid + s]) ? sv[tid] : sv[tid + s];
        __syncthreads();
    }
    unsigned long long m2 = sv[0];
    __syncthreads();
    sv[tid] = (v == m1 || v == m2) ? 0ull : v; __syncthreads();
    for (int s = 256; s > 0; s >>= 1) {
        if (tid < s) sv[tid] = (sv[tid] > sv[tid + s]) ? sv[tid] : sv[tid + s];
        __syncthreads();
    }
    if (tid == 0) {
        unsigned long long m3 = sv[0];
        unsigned c1 = 0xFFFFFFFFu - (unsigned)(m1 & 0xFFFFFFFFull);
        unsigned c2 = (m2 != 0ull) ? (0xFFFFFFFFu - (unsigned)(m2 & 0xFFFFFFFFull)) : c1;
        unsigned c3 = (m3 != 0ull) ? (0xFFFFFFFFu - (unsigned)(m3 & 0xFFFFFFFFull)) : c1;
        g_top[row] = make_uint4(c1, c2, c3, 0u);
    }
}

// ---------------- exact fp32 dots for top-3, pick true argmax ----------------
__global__ void gather_pick(const float* __restrict__ x, const float* __restrict__ w,
                            const float* __restrict__ rx, const float* __restrict__ rw) {
    __shared__ float sd[6];
    int row = blockIdx.x;
    int tid = threadIdx.x;
    int wrp = tid >> 5;         // 0..5: (model, cand) = (wrp/3, wrp%3)
    int lane = tid & 31;
    uint4 t = g_top[row];
    unsigned cols[3] = { t.x, t.y, t.z };
    unsigned col = cols[wrp % 3];
    const float* a = (wrp < 3) ? (x + (size_t)row * HH) : (rx + (size_t)row * HH);
    const float* b = (wrp < 3) ? (w + (size_t)col * HH) : (rw + (size_t)col * HH);
    float s = 0.0f;
    for (int h = lane; h < HH; h += 32) s = fmaf(a[h], b[h], s);
#pragma unroll
    for (int m = 16; m >= 1; m >>= 1) s += __shfl_xor_sync(0xFFFFFFFFu, s, m);
    if (lane == 0) sd[wrp] = s;
    __syncthreads();
    if (tid == 0) {
        int best = 0;
        for (int k = 1; k < 3; ++k) {
            if (sd[k] > sd[best] || (sd[k] == sd[best] && cols[k] < cols[best])) best = k;
        }
        g_pdot[row] = sd[best];
        g_rdot[row] = sd[3 + best];
    }
}

// ---------------- final scalar loss ----------------
__global__ void loss_kernel(const float* __restrict__ adv,
                            const float* __restrict__ oldlp,
                            const int*   __restrict__ mask,
                            float* __restrict__ out) {
    __shared__ float sl[256], sm[256];
    int tid = threadIdx.x;
    float accl = 0.0f, accm = 0.0f;
    for (int r = tid; r < BT; r += 256) {
        int b = r / TT;
        float lse_p = logf(g_sum_pol[r]);
        float lse_r = logf(g_sum_ref[r]);
        float chosen_lp = g_pdot[r] - lse_p;
        float ref_lp    = g_rdot[r] - lse_r;

        float c1 = expf(chosen_lp - oldlp[r]);
        float c2 = fminf(fmaxf(c1, 1.0f - EPS_LO_C), 1.0f + EPS_HI_C);
        float a  = adv[b];
        float ptl = -fminf(c1 * a, c2 * a);

        float delta = ref_lp - chosen_lp;
        float kl = expf(delta) - delta - 1.0f;
        ptl += BETA_C * kl;

        float m = (float)mask[r];
        accl += ptl * m;
        accm += m;
    }
    sl[tid] = accl; sm[tid] = accm;
    __syncthreads();
    for (int s = 128; s > 0; s >>= 1) {
        if (tid < s) { sl[tid] += sl[tid + s]; sm[tid] += sm[tid + s]; }
        __syncthreads();
    }
    if (tid == 0) out[0] = sl[0] / fmaxf(sm[0], 1.0f);
}

// ---------------- launch ----------------
extern "C" void kernel_launch(void* const* d_in, const int* in_sizes, int n_in,
                              void* d_out, int out_size) {
    const float* x    = (const float*)d_in[0];
    const float* w    = (const float*)d_in[1];
    const float* rx   = (const float*)d_in[2];
    const float* rw   = (const float*)d_in[3];
    const float* adv  = (const float*)d_in[4];
    const float* oldl = (const float*)d_in[5];
    const int*   msk  = (const int*)d_in[6];
    float* out = (float*)d_out;

    float *sum_pol, *sum_ref;
    unsigned long long* cand;
    __half *xh, *wh, *rxh, *rwh;
    cudaGetSymbolAddress((void**)&sum_pol, g_sum_pol);
    cudaGetSymbolAddress((void**)&sum_ref, g_sum_ref);
    cudaGetSymbolAddress((void**)&cand,    g_cand);
    cudaGetSymbolAddress((void**)&xh,  g_xh);
    cudaGetSymbolAddress((void**)&wh,  g_wh);
    cudaGetSymbolAddress((void**)&rxh, g_rxh);
    cudaGetSymbolAddress((void**)&rwh, g_rwh);

    cudaFuncSetAttribute(gemm_mma, cudaFuncAttributeMaxDynamicSharedMemorySize, SMEM_DYN);

    init_kernel<<<(BT * CANDP + 255) / 256, 256>>>();

    convert_all<<<(NTOT + 255) / 256, 256>>>(x, rx, w, rw, xh, rxh, wh, rwh);

    dim3 grid(BT / BM, VV / BN);   // (16, 500)
    gemm_mma<<<grid, GT, SMEM_DYN>>>(xh,  wh,  sum_pol, cand, 1);
    gemm_mma<<<grid, GT, SMEM_DYN>>>(rxh, rwh, sum_ref, cand, 0);

    top3_kernel<<<BT, 512>>>();
    gather_pick<<<BT, 192>>>(x, w, rx, rw);
    loss_kernel<<<1, 256>>>(adv, oldl, msk, out);
}